// round 16
// baseline (speedup 1.0000x reference)
#include <cuda_runtime.h>
#include <cuda_bf16.h>
#include <cstdint>

#define N_NODES 100000
#define MAX_EDGES 1600000
#define HEADS 8
#define OUT_CH 16
#define DIM 128            // IN_CH == OUT_DIM == 128
#define NEG_SLOPE 0.2f
#define LN_EPS 1e-5f

// ---------------- scratch (device globals; no allocation allowed) ----------
__device__ float g_h   [(size_t)N_NODES * DIM];   // x @ W   51.2 MB
__device__ float g_as  [N_NODES * HEADS];         // <h, att_src>
__device__ float g_ad  [N_NODES * HEADS];         // <h, att_dst>
__device__ int   g_cnt [N_NODES];                 // in-degree
__device__ int   g_off [N_NODES];                 // CSR offsets (exclusive)
__device__ int   g_cur [N_NODES];                 // scatter cursors
__device__ int   g_ssrc[MAX_EDGES];               // src ids sorted by dst

__device__ __forceinline__ float leaky(float v) { return v > 0.f ? v : NEG_SLOPE * v; }
__device__ __forceinline__ uint32_t pack_bf2(__nv_bfloat16 lo, __nv_bfloat16 hi) {
    return (uint32_t)__bfloat16_as_ushort(lo) | ((uint32_t)__bfloat16_as_ushort(hi) << 16);
}

#define MMA16816(C, a0, a1, a2, a3, b0, b1) \
    asm volatile("mma.sync.aligned.m16n8k16.row.col.f32.bf16.bf16.f32 " \
                 "{%0,%1,%2,%3}, {%4,%5,%6,%7}, {%8,%9}, {%0,%1,%2,%3};" \
                 : "+f"((C)[0]), "+f"((C)[1]), "+f"((C)[2]), "+f"((C)[3]) \
                 : "r"(a0), "r"(a1), "r"(a2), "r"(a3), "r"(b0), "r"(b1))

// ---------------- K1: split-bf16 HMMA GEMM (R15 layout, minus agg/den) ------
__global__ __launch_bounds__(256, 3) void k_gemm(const float* __restrict__ x,
                                                 const float* __restrict__ W,
                                                 const float* __restrict__ att_s,
                                                 const float* __restrict__ att_d, int N) {
    __shared__ uint2 whi[2048];   // 16 KB
    __shared__ uint2 wlo[2048];   // 16 KB

    const int tid = threadIdx.x;
    const int lane = tid & 31, w = tid >> 5;
    const int g = lane >> 2, q = lane & 3;
    const int nh = blockIdx.y;            // 0 or 1: which 64-col half
    const int n0 = nh * 64;

    for (int ent = tid; ent < 2048; ent += 256) {
        int jj = ent >> 8;
        int ks = (ent >> 5) & 7;
        int lt = ent & 31;
        int gg = lt >> 2, qq = lt & 3;
        int n = n0 + jj * 8 + gg;
        int k0 = ks * 16 + qq * 2;
        float w00 = W[k0 * 128 + n],       w01 = W[(k0 + 1) * 128 + n];
        float w10 = W[(k0 + 8) * 128 + n], w11 = W[(k0 + 9) * 128 + n];
        __nv_bfloat16 h00 = __float2bfloat16(w00), h01 = __float2bfloat16(w01);
        __nv_bfloat16 h10 = __float2bfloat16(w10), h11 = __float2bfloat16(w11);
        whi[ent] = make_uint2(pack_bf2(h00, h01), pack_bf2(h10, h11));
        wlo[ent] = make_uint2(
            pack_bf2(__float2bfloat16(w00 - __bfloat162float(h00)),
                     __float2bfloat16(w01 - __bfloat162float(h01))),
            pack_bf2(__float2bfloat16(w10 - __bfloat162float(h10)),
                     __float2bfloat16(w11 - __bfloat162float(h11))));
    }
    __syncthreads();

    const int r0g = blockIdx.x * 128 + w * 16 + g;
    const int r1g = r0g + 8;
    const bool v0 = r0g < N, v1 = r1g < N;
    const float* xr0 = &x[(size_t)r0g * DIM];
    const float* xr1 = &x[(size_t)r1g * DIM];
    const float2 z2 = make_float2(0.f, 0.f);

    float c[8][4];
#pragma unroll
    for (int j = 0; j < 8; j++) { c[j][0] = c[j][1] = c[j][2] = c[j][3] = 0.f; }

#pragma unroll
    for (int ks = 0; ks < 8; ks++) {
        int k0 = ks * 16 + q * 2;
        float2 fa = v0 ? *(const float2*)&xr0[k0]     : z2;
        float2 fc = v1 ? *(const float2*)&xr1[k0]     : z2;
        float2 fb = v0 ? *(const float2*)&xr0[k0 + 8] : z2;
        float2 fd = v1 ? *(const float2*)&xr1[k0 + 8] : z2;
        __nv_bfloat16 ha0 = __float2bfloat16(fa.x), ha1 = __float2bfloat16(fa.y);
        __nv_bfloat16 hc0 = __float2bfloat16(fc.x), hc1 = __float2bfloat16(fc.y);
        __nv_bfloat16 hb0 = __float2bfloat16(fb.x), hb1 = __float2bfloat16(fb.y);
        __nv_bfloat16 hd0 = __float2bfloat16(fd.x), hd1 = __float2bfloat16(fd.y);
        uint32_t ah0 = pack_bf2(ha0, ha1), ah1 = pack_bf2(hc0, hc1);
        uint32_t ah2 = pack_bf2(hb0, hb1), ah3 = pack_bf2(hd0, hd1);
        uint32_t al0 = pack_bf2(__float2bfloat16(fa.x - __bfloat162float(ha0)),
                                __float2bfloat16(fa.y - __bfloat162float(ha1)));
        uint32_t al1 = pack_bf2(__float2bfloat16(fc.x - __bfloat162float(hc0)),
                                __float2bfloat16(fc.y - __bfloat162float(hc1)));
        uint32_t al2 = pack_bf2(__float2bfloat16(fb.x - __bfloat162float(hb0)),
                                __float2bfloat16(fb.y - __bfloat162float(hb1)));
        uint32_t al3 = pack_bf2(__float2bfloat16(fd.x - __bfloat162float(hd0)),
                                __float2bfloat16(fd.y - __bfloat162float(hd1)));
#pragma unroll
        for (int jj = 0; jj < 8; jj++) {
            uint2 bh = whi[(jj * 8 + ks) * 32 + lane];
            uint2 bl = wlo[(jj * 8 + ks) * 32 + lane];
            MMA16816(c[jj], ah0, ah1, ah2, ah3, bh.x, bh.y);
            MMA16816(c[jj], ah0, ah1, ah2, ah3, bl.x, bl.y);
            MMA16816(c[jj], al0, al1, al2, al3, bh.x, bh.y);
        }
    }

    float asr0[4] = {}, asr1[4] = {}, adr0[4] = {}, adr1[4] = {};
#pragma unroll
    for (int jj = 0; jj < 8; jj++) {
        int h = jj >> 1;
        int cc = n0 + jj * 8 + q * 2;
        float s0 = att_s[cc], s1 = att_s[cc + 1];
        float d0 = att_d[cc], d1 = att_d[cc + 1];
        asr0[h] += c[jj][0] * s0 + c[jj][1] * s1;
        asr1[h] += c[jj][2] * s0 + c[jj][3] * s1;
        adr0[h] += c[jj][0] * d0 + c[jj][1] * d1;
        adr1[h] += c[jj][2] * d0 + c[jj][3] * d1;
    }
#pragma unroll
    for (int h = 0; h < 4; h++) {
        asr0[h] += __shfl_xor_sync(0xffffffffu, asr0[h], 1);
        asr0[h] += __shfl_xor_sync(0xffffffffu, asr0[h], 2);
        asr1[h] += __shfl_xor_sync(0xffffffffu, asr1[h], 1);
        asr1[h] += __shfl_xor_sync(0xffffffffu, asr1[h], 2);
        adr0[h] += __shfl_xor_sync(0xffffffffu, adr0[h], 1);
        adr0[h] += __shfl_xor_sync(0xffffffffu, adr0[h], 2);
        adr1[h] += __shfl_xor_sync(0xffffffffu, adr1[h], 1);
        adr1[h] += __shfl_xor_sync(0xffffffffu, adr1[h], 2);
    }

#pragma unroll
    for (int jj = 0; jj < 8; jj++) {
        int cc = n0 + jj * 8 + q * 2;
        if (v0) *(float2*)&g_h[(size_t)r0g * DIM + cc] = make_float2(c[jj][0], c[jj][1]);
        if (v1) *(float2*)&g_h[(size_t)r1g * DIM + cc] = make_float2(c[jj][2], c[jj][3]);
    }
    if (q == 0) {
        if (v0) {
            *(float4*)&g_as[r0g * 8 + nh * 4] = make_float4(asr0[0], asr0[1], asr0[2], asr0[3]);
            *(float4*)&g_ad[r0g * 8 + nh * 4] = make_float4(adr0[0], adr0[1], adr0[2], adr0[3]);
        }
        if (v1) {
            *(float4*)&g_as[r1g * 8 + nh * 4] = make_float4(asr1[0], asr1[1], asr1[2], asr1[3]);
            *(float4*)&g_ad[r1g * 8 + nh * 4] = make_float4(adr1[0], adr1[1], adr1[2], adr1[3]);
        }
    }
}

// ---------------- sort pipeline ---------------------------------------------
__global__ __launch_bounds__(256) void k_zero(int N) {
    int t = blockIdx.x * blockDim.x + threadIdx.x;
    if (t < N) g_cnt[t] = 0;
}
__global__ __launch_bounds__(256) void k_hist(const int* __restrict__ ei, int E) {
    int t = blockIdx.x * blockDim.x + threadIdx.x;
    if (t < E) atomicAdd(&g_cnt[ei[E + t]], 1);
}
// single-block exclusive scan over N counts -> g_off, g_cur
__global__ __launch_bounds__(1024) void k_scan(int N) {
    __shared__ int part[1024];
    int t = threadIdx.x;
    int chunk = (N + 1023) >> 10;
    int lo = t * chunk, hi = min(lo + chunk, N);
    int s = 0;
    for (int i = lo; i < hi; i++) s += g_cnt[i];
    part[t] = s;
    __syncthreads();
    for (int o = 1; o < 1024; o <<= 1) {
        int v = (t >= o) ? part[t - o] : 0;
        __syncthreads();
        part[t] += v;
        __syncthreads();
    }
    int base = (t == 0) ? 0 : part[t - 1];
    for (int i = lo; i < hi; i++) {
        g_off[i] = base;
        g_cur[i] = base;
        base += g_cnt[i];
    }
}
__global__ __launch_bounds__(256) void k_scatter(const int* __restrict__ ei, int E) {
    int t = blockIdx.x * blockDim.x + threadIdx.x;
    if (t < E) {
        int dst = ei[E + t];
        int p = atomicAdd(&g_cur[dst], 1);
        g_ssrc[p] = ei[t];
    }
}

// ---------------- K2: fused aggregate + softmax + LN + ELU (warp per node) --
__global__ __launch_bounds__(256) void k_agg(const float* __restrict__ bias,
                                             const float* __restrict__ gamma,
                                             const float* __restrict__ beta,
                                             float* __restrict__ out, int N) {
    int i = (blockIdx.x * blockDim.x + threadIdx.x) >> 5;    // dst node
    int lane = threadIdx.x & 31;
    if (i >= N) return;
    int hd = lane >> 2;

    int off = g_off[i];
    int deg = g_cnt[i];
    float ad_i = g_ad[i * HEADS + hd];

    float4 acc = make_float4(0.f, 0.f, 0.f, 0.f);
    float den = 0.f;

    for (int base = 0; base < deg; base += 8) {
        int s = 0;
        if (lane < 8 && base + lane < deg) s = g_ssrc[off + base + lane];
        int rem = deg - base;
        if (rem >= 8) {
#pragma unroll
            for (int j = 0; j < 8; j++) {
                int src = __shfl_sync(0xffffffffu, s, j);
                float e_ = __expf(leaky(g_as[src * HEADS + hd] + ad_i));
                float4 hv = *(const float4*)&g_h[(size_t)src * DIM + lane * 4];
                acc.x += e_ * hv.x; acc.y += e_ * hv.y;
                acc.z += e_ * hv.z; acc.w += e_ * hv.w;
                den += e_;
            }
        } else {
            for (int j = 0; j < rem; j++) {
                int src = __shfl_sync(0xffffffffu, s, j);
                float e_ = __expf(leaky(g_as[src * HEADS + hd] + ad_i));
                float4 hv = *(const float4*)&g_h[(size_t)src * DIM + lane * 4];
                acc.x += e_ * hv.x; acc.y += e_ * hv.y;
                acc.z += e_ * hv.z; acc.w += e_ * hv.w;
                den += e_;
            }
        }
    }

    // self-loop
    float exs = __expf(leaky(g_as[i * HEADS + hd] + ad_i));
    float4 hs = *(const float4*)&g_h[(size_t)i * DIM + lane * 4];
    acc.x += exs * hs.x; acc.y += exs * hs.y;
    acc.z += exs * hs.z; acc.w += exs * hs.w;
    den += exs;

    float rden = __frcp_rn(den);
    float4 bi = *(const float4*)&bias[lane * 4];
    float4 v;
    v.x = acc.x * rden + bi.x;
    v.y = acc.y * rden + bi.y;
    v.z = acc.z * rden + bi.z;
    v.w = acc.w * rden + bi.w;

    float s = v.x + v.y + v.z + v.w;
    float q = v.x * v.x + v.y * v.y + v.z * v.z + v.w * v.w;
#pragma unroll
    for (int o = 16; o > 0; o >>= 1) {
        s += __shfl_xor_sync(0xffffffffu, s, o);
        q += __shfl_xor_sync(0xffffffffu, q, o);
    }
    float mu = s * (1.f / DIM);
    float rsd = rsqrtf(q * (1.f / DIM) - mu * mu + LN_EPS);

    float4 ga = *(const float4*)&gamma[lane * 4];
    float4 be = *(const float4*)&beta[lane * 4];
    float4 y;
    y.x = (v.x - mu) * rsd * ga.x + be.x;
    y.y = (v.y - mu) * rsd * ga.y + be.y;
    y.z = (v.z - mu) * rsd * ga.z + be.z;
    y.w = (v.w - mu) * rsd * ga.w + be.w;
    y.x = y.x > 0.f ? y.x : (__expf(y.x) - 1.f);
    y.y = y.y > 0.f ? y.y : (__expf(y.y) - 1.f);
    y.z = y.z > 0.f ? y.z : (__expf(y.z) - 1.f);
    y.w = y.w > 0.f ? y.w : (__expf(y.w) - 1.f);
    *(float4*)&out[(size_t)i * DIM + lane * 4] = y;
}

// ---------------- launch ----------------------------------------------------
extern "C" void kernel_launch(void* const* d_in, const int* in_sizes, int n_in,
                              void* d_out, int out_size) {
    const float* x     = (const float*)d_in[0];
    const int*   ei    = (const int*)d_in[1];      // int64 in reference -> int32 in harness
    const float* W     = (const float*)d_in[2];
    const float* att_s = (const float*)d_in[3];
    const float* att_d = (const float*)d_in[4];
    const float* bias  = (const float*)d_in[5];
    const float* gamma = (const float*)d_in[6];
    const float* beta  = (const float*)d_in[7];
    float* out = (float*)d_out;

    const int N = in_sizes[0] / DIM;       // 100000
    const int E = in_sizes[1] / 2;         // 1600000

    // CSR build (independent of gemm)
    k_zero   <<<(N + 255) / 256, 256>>>(N);
    k_hist   <<<(E + 255) / 256, 256>>>(ei, E);
    k_scan   <<<1, 1024>>>(N);
    k_scatter<<<(E + 255) / 256, 256>>>(ei, E);

    dim3 gg((N + 127) / 128, 2);
    k_gemm <<<gg, 256>>>(x, W, att_s, att_d, N);

    k_agg  <<<(N * 32 + 255) / 256, 256>>>(bias, gamma, beta, out, N);
}

// round 17
// speedup vs baseline: 1.3703x; 1.3703x over previous
#include <cuda_runtime.h>
#include <cuda_bf16.h>
#include <cuda_fp16.h>
#include <cstdint>

#define N_NODES 100000
#define HEADS 8
#define OUT_CH 16
#define DIM 128            // IN_CH == OUT_DIM == 128
#define NEG_SLOPE 0.2f
#define LN_EPS 1e-5f

// ---------------- scratch (device globals; no allocation allowed) ----------
__device__ float  g_h   [(size_t)N_NODES * DIM];   // x @ W   51.2 MB (fp32, self-loop/final)
__device__ __half g_hh  [(size_t)N_NODES * DIM];   // fp16 image for edge gathers 25.6 MB
__device__ float  g_agg [(size_t)N_NODES * DIM];   // unnorm. message  51.2 MB
__device__ float  g_as  [N_NODES * HEADS];         // <h, att_src>
__device__ float  g_ad  [N_NODES * HEADS];         // <h, att_dst>
__device__ float  g_den [N_NODES * HEADS];         // softmax denom (unnorm)

__device__ __forceinline__ float leaky(float v) { return v > 0.f ? v : NEG_SLOPE * v; }
__device__ __forceinline__ uint32_t pack_bf2(__nv_bfloat16 lo, __nv_bfloat16 hi) {
    return (uint32_t)__bfloat16_as_ushort(lo) | ((uint32_t)__bfloat16_as_ushort(hi) << 16);
}

#define MMA16816(C, a0, a1, a2, a3, b0, b1) \
    asm volatile("mma.sync.aligned.m16n8k16.row.col.f32.bf16.bf16.f32 " \
                 "{%0,%1,%2,%3}, {%4,%5,%6,%7}, {%8,%9}, {%0,%1,%2,%3};" \
                 : "+f"((C)[0]), "+f"((C)[1]), "+f"((C)[2]), "+f"((C)[3]) \
                 : "r"(a0), "r"(a1), "r"(a2), "r"(a3), "r"(b0), "r"(b1))

// ---------------- K1: split-bf16 HMMA GEMM (R15 layout + fp16 image) --------
__global__ __launch_bounds__(256, 3) void k_gemm(const float* __restrict__ x,
                                                 const float* __restrict__ W,
                                                 const float* __restrict__ att_s,
                                                 const float* __restrict__ att_d, int N) {
    __shared__ uint2 whi[2048];   // 16 KB
    __shared__ uint2 wlo[2048];   // 16 KB

    const int tid = threadIdx.x;
    const int lane = tid & 31, w = tid >> 5;
    const int g = lane >> 2, q = lane & 3;
    const int nh = blockIdx.y;            // 0 or 1: which 64-col half
    const int n0 = nh * 64;

    for (int ent = tid; ent < 2048; ent += 256) {
        int jj = ent >> 8;
        int ks = (ent >> 5) & 7;
        int lt = ent & 31;
        int gg = lt >> 2, qq = lt & 3;
        int n = n0 + jj * 8 + gg;
        int k0 = ks * 16 + qq * 2;
        float w00 = W[k0 * 128 + n],       w01 = W[(k0 + 1) * 128 + n];
        float w10 = W[(k0 + 8) * 128 + n], w11 = W[(k0 + 9) * 128 + n];
        __nv_bfloat16 h00 = __float2bfloat16(w00), h01 = __float2bfloat16(w01);
        __nv_bfloat16 h10 = __float2bfloat16(w10), h11 = __float2bfloat16(w11);
        whi[ent] = make_uint2(pack_bf2(h00, h01), pack_bf2(h10, h11));
        wlo[ent] = make_uint2(
            pack_bf2(__float2bfloat16(w00 - __bfloat162float(h00)),
                     __float2bfloat16(w01 - __bfloat162float(h01))),
            pack_bf2(__float2bfloat16(w10 - __bfloat162float(h10)),
                     __float2bfloat16(w11 - __bfloat162float(h11))));
    }
    __syncthreads();

    const int r0g = blockIdx.x * 128 + w * 16 + g;
    const int r1g = r0g + 8;
    const bool v0 = r0g < N, v1 = r1g < N;
    const float* xr0 = &x[(size_t)r0g * DIM];
    const float* xr1 = &x[(size_t)r1g * DIM];
    const float2 z2 = make_float2(0.f, 0.f);

    float c[8][4];
#pragma unroll
    for (int j = 0; j < 8; j++) { c[j][0] = c[j][1] = c[j][2] = c[j][3] = 0.f; }

#pragma unroll
    for (int ks = 0; ks < 8; ks++) {
        int k0 = ks * 16 + q * 2;
        float2 fa = v0 ? *(const float2*)&xr0[k0]     : z2;
        float2 fc = v1 ? *(const float2*)&xr1[k0]     : z2;
        float2 fb = v0 ? *(const float2*)&xr0[k0 + 8] : z2;
        float2 fd = v1 ? *(const float2*)&xr1[k0 + 8] : z2;
        __nv_bfloat16 ha0 = __float2bfloat16(fa.x), ha1 = __float2bfloat16(fa.y);
        __nv_bfloat16 hc0 = __float2bfloat16(fc.x), hc1 = __float2bfloat16(fc.y);
        __nv_bfloat16 hb0 = __float2bfloat16(fb.x), hb1 = __float2bfloat16(fb.y);
        __nv_bfloat16 hd0 = __float2bfloat16(fd.x), hd1 = __float2bfloat16(fd.y);
        uint32_t ah0 = pack_bf2(ha0, ha1), ah1 = pack_bf2(hc0, hc1);
        uint32_t ah2 = pack_bf2(hb0, hb1), ah3 = pack_bf2(hd0, hd1);
        uint32_t al0 = pack_bf2(__float2bfloat16(fa.x - __bfloat162float(ha0)),
                                __float2bfloat16(fa.y - __bfloat162float(ha1)));
        uint32_t al1 = pack_bf2(__float2bfloat16(fc.x - __bfloat162float(hc0)),
                                __float2bfloat16(fc.y - __bfloat162float(hc1)));
        uint32_t al2 = pack_bf2(__float2bfloat16(fb.x - __bfloat162float(hb0)),
                                __float2bfloat16(fb.y - __bfloat162float(hb1)));
        uint32_t al3 = pack_bf2(__float2bfloat16(fd.x - __bfloat162float(hd0)),
                                __float2bfloat16(fd.y - __bfloat162float(hd1)));
#pragma unroll
        for (int jj = 0; jj < 8; jj++) {
            uint2 bh = whi[(jj * 8 + ks) * 32 + lane];
            uint2 bl = wlo[(jj * 8 + ks) * 32 + lane];
            MMA16816(c[jj], ah0, ah1, ah2, ah3, bh.x, bh.y);
            MMA16816(c[jj], ah0, ah1, ah2, ah3, bl.x, bl.y);
            MMA16816(c[jj], al0, al1, al2, al3, bh.x, bh.y);
        }
    }

    float asr0[4] = {}, asr1[4] = {}, adr0[4] = {}, adr1[4] = {};
#pragma unroll
    for (int jj = 0; jj < 8; jj++) {
        int h = jj >> 1;
        int cc = n0 + jj * 8 + q * 2;
        float s0 = att_s[cc], s1 = att_s[cc + 1];
        float d0 = att_d[cc], d1 = att_d[cc + 1];
        asr0[h] += c[jj][0] * s0 + c[jj][1] * s1;
        asr1[h] += c[jj][2] * s0 + c[jj][3] * s1;
        adr0[h] += c[jj][0] * d0 + c[jj][1] * d1;
        adr1[h] += c[jj][2] * d0 + c[jj][3] * d1;
    }
#pragma unroll
    for (int h = 0; h < 4; h++) {
        asr0[h] += __shfl_xor_sync(0xffffffffu, asr0[h], 1);
        asr0[h] += __shfl_xor_sync(0xffffffffu, asr0[h], 2);
        asr1[h] += __shfl_xor_sync(0xffffffffu, asr1[h], 1);
        asr1[h] += __shfl_xor_sync(0xffffffffu, asr1[h], 2);
        adr0[h] += __shfl_xor_sync(0xffffffffu, adr0[h], 1);
        adr0[h] += __shfl_xor_sync(0xffffffffu, adr0[h], 2);
        adr1[h] += __shfl_xor_sync(0xffffffffu, adr1[h], 1);
        adr1[h] += __shfl_xor_sync(0xffffffffu, adr1[h], 2);
    }

    // ---- stores: g_h fp32 + g_hh fp16 + zero g_agg for this 64-col half
#pragma unroll
    for (int jj = 0; jj < 8; jj++) {
        int cc = n0 + jj * 8 + q * 2;
        if (v0) {
            *(float2*)&g_h  [(size_t)r0g * DIM + cc] = make_float2(c[jj][0], c[jj][1]);
            *(float2*)&g_agg[(size_t)r0g * DIM + cc] = z2;
            *(__half2*)&g_hh[(size_t)r0g * DIM + cc] = __floats2half2_rn(c[jj][0], c[jj][1]);
        }
        if (v1) {
            *(float2*)&g_h  [(size_t)r1g * DIM + cc] = make_float2(c[jj][2], c[jj][3]);
            *(float2*)&g_agg[(size_t)r1g * DIM + cc] = z2;
            *(__half2*)&g_hh[(size_t)r1g * DIM + cc] = __floats2half2_rn(c[jj][2], c[jj][3]);
        }
    }
    if (q == 0) {
        const float4 z4 = make_float4(0.f, 0.f, 0.f, 0.f);
        if (v0) {
            *(float4*)&g_as [r0g * 8 + nh * 4] = make_float4(asr0[0], asr0[1], asr0[2], asr0[3]);
            *(float4*)&g_ad [r0g * 8 + nh * 4] = make_float4(adr0[0], adr0[1], adr0[2], adr0[3]);
            *(float4*)&g_den[r0g * 8 + nh * 4] = z4;
        }
        if (v1) {
            *(float4*)&g_as [r1g * 8 + nh * 4] = make_float4(asr1[0], asr1[1], asr1[2], asr1[3]);
            *(float4*)&g_ad [r1g * 8 + nh * 4] = make_float4(adr1[0], adr1[1], adr1[2], adr1[3]);
            *(float4*)&g_den[r1g * 8 + nh * 4] = z4;
        }
    }
}

// ---------------- K2: edge accumulate (8 edges per warp, fp16 gather) -------
#define EPW 8
__global__ __launch_bounds__(256) void k_acc(const int* __restrict__ ei, int E) {
    int warp = (blockIdx.x * blockDim.x + threadIdx.x) >> 5;
    int lane = threadIdx.x & 31;
    int e0 = warp * EPW;
    if (e0 >= E) return;

    int idx = 0;
    if (lane < 8) {
        int e = e0 + lane;
        idx = (e < E) ? ei[e] : 0;
    } else if (lane < 16) {
        int e = e0 + lane - 8;
        idx = (e < E) ? ei[E + e] : 0;
    }

    int hd = lane & 7;
    float ex[2];
#pragma unroll
    for (int j = 0; j < 2; j++) {
        int el = j * 4 + (lane >> 3);
        int src_l = __shfl_sync(0xffffffffu, idx, el);
        int dst_l = __shfl_sync(0xffffffffu, idx, 8 + el);
        ex[j] = 0.f;
        if (e0 + el < E) {
            ex[j] = __expf(leaky(g_as[src_l * HEADS + hd] + g_ad[dst_l * HEADS + hd]));
            atomicAdd(&g_den[dst_l * HEADS + hd], ex[j]);
        }
    }
#pragma unroll
    for (int e = 0; e < EPW; e++) {
        if (e0 + e >= E) break;
        int src = __shfl_sync(0xffffffffu, idx, e);
        int dst = __shfl_sync(0xffffffffu, idx, 8 + e);
        float exh = __shfl_sync(0xffffffffu, ex[e >> 2], (e & 3) * 8 + (lane >> 2));
        // fp16 gather: 4 halves = 8B per lane
        uint2 raw = *(const uint2*)&g_hh[(size_t)src * DIM + lane * 4];
        float2 f01 = __half22float2(*(const __half2*)&raw.x);
        float2 f23 = __half22float2(*(const __half2*)&raw.y);
        size_t gp = __cvta_generic_to_global(&g_agg[(size_t)dst * DIM + lane * 4]);
        asm volatile("red.global.add.v4.f32 [%0], {%1,%2,%3,%4};"
                     :: "l"(gp), "f"(exh * f01.x), "f"(exh * f01.y),
                        "f"(exh * f23.x), "f"(exh * f23.y)
                     : "memory");
    }
}

// ---------------- K3: warp per node, float4 per lane ------------------------
__global__ __launch_bounds__(256) void k_final(const float* __restrict__ bias,
                                               const float* __restrict__ gamma,
                                               const float* __restrict__ beta,
                                               float* __restrict__ out, int N) {
    int i = (blockIdx.x * blockDim.x + threadIdx.x) >> 5;
    int lane = threadIdx.x & 31;
    if (i >= N) return;
    int hd = lane >> 2;

    float exs = __expf(leaky(g_as[i * HEADS + hd] + g_ad[i * HEADS + hd]));
    float rden = __frcp_rn(g_den[i * HEADS + hd] + exs);

    float4 ag = *(const float4*)&g_agg[(size_t)i * DIM + lane * 4];
    float4 hv = *(const float4*)&g_h[(size_t)i * DIM + lane * 4];
    float4 bi = *(const float4*)&bias[lane * 4];
    float4 v;
    v.x = (ag.x + exs * hv.x) * rden + bi.x;
    v.y = (ag.y + exs * hv.y) * rden + bi.y;
    v.z = (ag.z + exs * hv.z) * rden + bi.z;
    v.w = (ag.w + exs * hv.w) * rden + bi.w;

    float s = v.x + v.y + v.z + v.w;
    float q = v.x * v.x + v.y * v.y + v.z * v.z + v.w * v.w;
#pragma unroll
    for (int o = 16; o > 0; o >>= 1) {
        s += __shfl_xor_sync(0xffffffffu, s, o);
        q += __shfl_xor_sync(0xffffffffu, q, o);
    }
    float mu = s * (1.f / DIM);
    float rsd = rsqrtf(q * (1.f / DIM) - mu * mu + LN_EPS);

    float4 ga = *(const float4*)&gamma[lane * 4];
    float4 be = *(const float4*)&beta[lane * 4];
    float4 y;
    y.x = (v.x - mu) * rsd * ga.x + be.x;
    y.y = (v.y - mu) * rsd * ga.y + be.y;
    y.z = (v.z - mu) * rsd * ga.z + be.z;
    y.w = (v.w - mu) * rsd * ga.w + be.w;
    y.x = y.x > 0.f ? y.x : (__expf(y.x) - 1.f);
    y.y = y.y > 0.f ? y.y : (__expf(y.y) - 1.f);
    y.z = y.z > 0.f ? y.z : (__expf(y.z) - 1.f);
    y.w = y.w > 0.f ? y.w : (__expf(y.w) - 1.f);
    *(float4*)&out[(size_t)i * DIM + lane * 4] = y;
}

// ---------------- launch ----------------------------------------------------
extern "C" void kernel_launch(void* const* d_in, const int* in_sizes, int n_in,
                              void* d_out, int out_size) {
    const float* x     = (const float*)d_in[0];
    const int*   ei    = (const int*)d_in[1];      // int64 in reference -> int32 in harness
    const float* W     = (const float*)d_in[2];
    const float* att_s = (const float*)d_in[3];
    const float* att_d = (const float*)d_in[4];
    const float* bias  = (const float*)d_in[5];
    const float* gamma = (const float*)d_in[6];
    const float* beta  = (const float*)d_in[7];
    float* out = (float*)d_out;

    const int N = in_sizes[0] / DIM;       // 100000
    const int E = in_sizes[1] / 2;         // 1600000

    dim3 gg((N + 127) / 128, 2);
    k_gemm <<<gg, 256>>>(x, W, att_s, att_d, N);
    int warps = (E + EPW - 1) / EPW;
    k_acc  <<<(warps * 32 + 255) / 256, 256>>>(ei, E);
    k_final<<<(N * 32 + 255) / 256, 256>>>(bias, gamma, beta, out, N);
}